// round 9
// baseline (speedup 1.0000x reference)
#include <cuda_runtime.h>
#include <cuda_fp16.h>

// Problem constants (fixed by the reference)
#define NN   50000
#define NE   800000
#define DIN  128
#define DHID 128
#define DOUT 64

// ---------------------------------------------------------------------------
// Static device scratch (no allocation allowed)
// ---------------------------------------------------------------------------
__device__ int    g_total;                    // running CSR offset (reset in count)
__device__ int    g_deg[NN];                  // zero at start of every replay (self-clean)
__device__ int    g_degs[NN];                 // saved degree for gather
__device__ int    g_cur[NN];
__device__ int    g_rowbeg[NN];               // CSR range start (unordered alloc)
__device__ int2   g_edge[NE];                 // CSR: {src, norm-as-int} per in-edge
__device__ float  g_dinv[NN];                 // rsqrt(1 + in_degree)
__device__ uint4  g_t16[NN * DHID / 8];       // transform buffer (8 x fp16 per uint4)
__device__ uint4  g_h16[NN * DHID / 8];       // aggregation buffer (8 x fp16 per uint4)

// ---------------------------------------------------------------------------
// f32x2 packed FMA helpers (Blackwell FFMA2 — only reachable via PTX)
// ---------------------------------------------------------------------------
__device__ __forceinline__ unsigned long long pack2(float x) {
    unsigned long long r;
    asm("mov.b64 %0, {%1, %2};" : "=l"(r) : "f"(x), "f"(x));
    return r;
}
__device__ __forceinline__ void fma2(unsigned long long& d,
                                     unsigned long long a, unsigned long long b) {
    asm("fma.rn.f32x2 %0, %1, %2, %0;" : "+l"(d) : "l"(a), "l"(b));
}
__device__ __forceinline__ float2 unpack2(unsigned long long v) {
    float2 f;
    asm("mov.b64 {%0, %1}, %2;" : "=f"(f.x), "=f"(f.y) : "l"(v));
    return f;
}

// ---------------------------------------------------------------------------
// Inline edge-index dtype detection: 4 entries read as int64. True int64
// indices are all in [0, NN); int32 data reinterpreted as int64 only passes
// if every odd word is zero (p ~ (2e-5)^4 ~ 1.6e-19). Broadcast loads, cheap.
// ---------------------------------------------------------------------------
__device__ __forceinline__ bool detect64(const void* __restrict__ ei) {
    const long long* p = (const long long*)ei;
    #pragma unroll
    for (int k = 0; k < 4; k++) {
        long long v = __ldg(&p[k]);
        if (v < 0 || v >= NN) return false;
    }
    return true;
}

// ---------------------------------------------------------------------------
// CSR construction (3 kernels: count -> alloc -> fill)
// ---------------------------------------------------------------------------
// 2 edges per thread; one thread resets g_total for this replay
__global__ void deg_count_kernel(const void* __restrict__ ei) {
    int e2 = blockIdx.x * blockDim.x + threadIdx.x;   // over NE/2
    if (blockIdx.x == 0 && threadIdx.x == 0) g_total = 0;
    if (e2 >= NE / 2) return;
    int d0, d1;
    if (detect64(ei)) {
        longlong2 d = ((const longlong2*)ei)[NE / 2 + e2];
        d0 = (int)d.x; d1 = (int)d.y;
    } else {
        int2 d = ((const int2*)ei)[NE / 2 + e2];
        d0 = d.x; d1 = d.y;
    }
    atomicAdd(&g_deg[d0], 1);
    atomicAdd(&g_deg[d1], 1);
}

// Unordered CSR range allocation; self-cleans g_deg for the next replay.
__global__ void alloc_kernel() {
    int i = blockIdx.x * blockDim.x + threadIdx.x;
    if (i < NN) {
        int d = g_deg[i];
        g_deg[i]    = 0;                      // invariant: zero at next replay start
        g_degs[i]   = d;
        g_rowbeg[i] = atomicAdd(&g_total, d);
        g_dinv[i]   = rsqrtf(1.0f + (float)d);
        g_cur[i]    = 0;
    }
}

// 2 edges per thread; writes packed {src, dinv[src]*dinv[dst]}
__global__ void fill_kernel(const void* __restrict__ ei) {
    int e2 = blockIdx.x * blockDim.x + threadIdx.x;   // over NE/2
    if (e2 >= NE / 2) return;
    int s0, s1, d0, d1;
    if (detect64(ei)) {
        longlong2 s = ((const longlong2*)ei)[e2];
        longlong2 d = ((const longlong2*)ei)[NE / 2 + e2];
        s0 = (int)s.x; s1 = (int)s.y; d0 = (int)d.x; d1 = (int)d.y;
    } else {
        int2 s = ((const int2*)ei)[e2];
        int2 d = ((const int2*)ei)[NE / 2 + e2];
        s0 = s.x; s1 = s.y; d0 = d.x; d1 = d.y;
    }
    float n0 = g_dinv[s0] * g_dinv[d0];
    float n1 = g_dinv[s1] * g_dinv[d1];
    int p0 = g_rowbeg[d0] + atomicAdd(&g_cur[d0], 1);
    int p1 = g_rowbeg[d1] + atomicAdd(&g_cur[d1], 1);
    g_edge[p0] = make_int2(s0, __float_as_int(n0));
    g_edge[p1] = make_int2(s1, __float_as_int(n1));
}

// ---------------------------------------------------------------------------
// GEMM: Y[M, DO] = X[M, K] @ W[K, DO]
// 64 rows/block, 256 threads, W + X tile in SMEM, FFMA2 accumulation.
// HALF_IN: X is fp16 (converted to fp32 in SMEM). Output is fp16 (half2).
// ---------------------------------------------------------------------------
template <int K, int DO, bool HALF_IN>
__global__ void gemm_kernel(const void* __restrict__ X,
                            const float* __restrict__ W,
                            void* __restrict__ Y, int M) {
    extern __shared__ float sm[];
    float* Ws = sm;            // K * DO
    float* Xs = sm + K * DO;   // 64 * K

    const int tid = threadIdx.x;
    const int bm  = blockIdx.x * 64;

    #pragma unroll 4
    for (int i = tid; i < K * DO / 4; i += 256)
        ((float4*)Ws)[i] = ((const float4*)W)[i];

    #pragma unroll 4
    for (int i = tid; i < 64 * K / 4; i += 256) {
        int row  = i / (K / 4);
        int col4 = i % (K / 4);
        float4 v = make_float4(0.f, 0.f, 0.f, 0.f);
        if (bm + row < M) {
            if (HALF_IN) {
                uint2 rv = *(const uint2*)((const __half*)X + (size_t)(bm + row) * K + col4 * 4);
                float2 a = __half22float2(*(__half2*)&rv.x);
                float2 b = __half22float2(*(__half2*)&rv.y);
                v = make_float4(a.x, a.y, b.x, b.y);
            } else {
                v = ((const float4*)((const float*)X + (size_t)(bm + row) * K))[col4];
            }
        }
        ((float4*)Xs)[i] = v;
    }
    __syncthreads();

    const int tx = tid & 31;
    const int ty = tid >> 5;           // 0..7
    constexpr int CP2 = DO / 64;       // column pairs per thread

    unsigned long long acc[8][CP2];
    #pragma unroll
    for (int r = 0; r < 8; r++)
        #pragma unroll
        for (int c = 0; c < CP2; c++) acc[r][c] = 0ull;

    for (int k = 0; k < K; k += 4) {
        float4 xv[8];
        #pragma unroll
        for (int r = 0; r < 8; r++)
            xv[r] = *(const float4*)&Xs[(ty * 8 + r) * K + k];

        #pragma unroll
        for (int kk = 0; kk < 4; kk++) {
            unsigned long long wv[CP2];
            #pragma unroll
            for (int c = 0; c < CP2; c++)
                wv[c] = *(const unsigned long long*)&Ws[(k + kk) * DO + 2 * tx + 64 * c];
            #pragma unroll
            for (int r = 0; r < 8; r++) {
                float xs = (kk == 0) ? xv[r].x : (kk == 1) ? xv[r].y
                         : (kk == 2) ? xv[r].z : xv[r].w;
                unsigned long long xp = pack2(xs);
                #pragma unroll
                for (int c = 0; c < CP2; c++)
                    fma2(acc[r][c], xp, wv[c]);
            }
        }
    }

    #pragma unroll
    for (int r = 0; r < 8; r++) {
        int row = bm + ty * 8 + r;
        if (row < M) {
            #pragma unroll
            for (int c = 0; c < CP2; c++) {
                float2 v = unpack2(acc[r][c]);
                size_t off = (size_t)row * DO + 2 * tx + 64 * c;
                *(__half2*)((__half*)Y + off) = __floats2half2_rn(v.x, v.y);
            }
        }
    }
}

// ---------------------------------------------------------------------------
// fp16 row fragment FMA: 8 features per thread
// ---------------------------------------------------------------------------
__device__ __forceinline__ void fma8(float* acc, uint4 raw, float n) {
    float2 p0 = __half22float2(*(__half2*)&raw.x);
    float2 p1 = __half22float2(*(__half2*)&raw.y);
    float2 p2 = __half22float2(*(__half2*)&raw.z);
    float2 p3 = __half22float2(*(__half2*)&raw.w);
    acc[0] = fmaf(p0.x, n, acc[0]); acc[1] = fmaf(p0.y, n, acc[1]);
    acc[2] = fmaf(p1.x, n, acc[2]); acc[3] = fmaf(p1.y, n, acc[3]);
    acc[4] = fmaf(p2.x, n, acc[4]); acc[5] = fmaf(p2.y, n, acc[5]);
    acc[6] = fmaf(p3.x, n, acc[6]); acc[7] = fmaf(p3.y, n, acc[7]);
}

// ---------------------------------------------------------------------------
// Gather layer 1 (self-loop + bias + ReLU), fp16 in / fp16 out:
// Each thread owns 8 features (one uint4); D/8 threads per node.
// ---------------------------------------------------------------------------
template <int D, int NPB>   // NPB * (D/8) == 128
__global__ void gather_kernel(const uint4* __restrict__ t16,
                              const float* __restrict__ bias,
                              uint4* __restrict__ h16) {
    constexpr int D8 = D / 8;
    const int ln   = threadIdx.x / D8;
    const int f8   = threadIdx.x % D8;
    const int node = blockIdx.x * NPB + ln;
    if (node >= NN) return;

    const float di  = g_dinv[node];
    const int   beg = g_rowbeg[node];
    const int   end = beg + g_degs[node];

    float acc[8] = {0, 0, 0, 0, 0, 0, 0, 0};
    fma8(acc, t16[(size_t)node * D8 + f8], di * di);   // self loop

    int e = beg;
    for (; e + 4 <= end; e += 4) {
        int2 e0 = __ldg(&g_edge[e]);
        int2 e1 = __ldg(&g_edge[e + 1]);
        int2 e2 = __ldg(&g_edge[e + 2]);
        int2 e3 = __ldg(&g_edge[e + 3]);
        uint4 r0 = t16[(size_t)e0.x * D8 + f8];
        uint4 r1 = t16[(size_t)e1.x * D8 + f8];
        uint4 r2 = t16[(size_t)e2.x * D8 + f8];
        uint4 r3 = t16[(size_t)e3.x * D8 + f8];
        fma8(acc, r0, __int_as_float(e0.y));
        fma8(acc, r1, __int_as_float(e1.y));
        fma8(acc, r2, __int_as_float(e2.y));
        fma8(acc, r3, __int_as_float(e3.y));
    }
    for (; e < end; e++) {
        int2 ev = __ldg(&g_edge[e]);
        fma8(acc, t16[(size_t)ev.x * D8 + f8], __int_as_float(ev.y));
    }

    float4 b0 = *(const float4*)&bias[8 * f8];
    float4 b1 = *(const float4*)&bias[8 * f8 + 4];
    uint4 o;
    *(__half2*)&o.x = __floats2half2_rn(fmaxf(acc[0] + b0.x, 0.f), fmaxf(acc[1] + b0.y, 0.f));
    *(__half2*)&o.y = __floats2half2_rn(fmaxf(acc[2] + b0.z, 0.f), fmaxf(acc[3] + b0.w, 0.f));
    *(__half2*)&o.z = __floats2half2_rn(fmaxf(acc[4] + b1.x, 0.f), fmaxf(acc[5] + b1.y, 0.f));
    *(__half2*)&o.w = __floats2half2_rn(fmaxf(acc[6] + b1.z, 0.f), fmaxf(acc[7] + b1.w, 0.f));
    h16[(size_t)node * D8 + f8] = o;
}

// ---------------------------------------------------------------------------
// Fused gather layer 2 + final FC:
//   hrow = relu(agg2(t) + b2);  out[node,:] = hrow @ fcW + fcb
// 128 threads = 16 nodes x 8 threads (D=64). fcW SMEM-resident.
// 3125 blocks x 16 nodes == 50000 exactly (no tail).
// ---------------------------------------------------------------------------
__global__ void gather_fc_kernel(const uint4* __restrict__ t16,
                                 const float* __restrict__ b2,
                                 const float* __restrict__ fcW,
                                 const float* __restrict__ fcb,
                                 float* __restrict__ out) {
    __shared__ float fcWs[64 * 64];
    __shared__ float hs[16 * 65];   // padded rows: no bank conflicts

    #pragma unroll 4
    for (int i = threadIdx.x; i < 64 * 64 / 4; i += 128)
        ((float4*)fcWs)[i] = ((const float4*)fcW)[i];

    const int ln   = threadIdx.x >> 3;      // 0..15
    const int f8   = threadIdx.x & 7;       // 0..7
    const int node = blockIdx.x * 16 + ln;  // always < NN

    const float di  = g_dinv[node];
    const int   beg = g_rowbeg[node];
    const int   end = beg + g_degs[node];

    float acc[8] = {0, 0, 0, 0, 0, 0, 0, 0};
    fma8(acc, t16[(size_t)node * 8 + f8], di * di);   // self loop

    int e = beg;
    for (; e + 4 <= end; e += 4) {
        int2 e0 = __ldg(&g_edge[e]);
        int2 e1 = __ldg(&g_edge[e + 1]);
        int2 e2 = __ldg(&g_edge[e + 2]);
        int2 e3 = __ldg(&g_edge[e + 3]);
        uint4 r0 = t16[(size_t)e0.x * 8 + f8];
        uint4 r1 = t16[(size_t)e1.x * 8 + f8];
        uint4 r2 = t16[(size_t)e2.x * 8 + f8];
        uint4 r3 = t16[(size_t)e3.x * 8 + f8];
        fma8(acc, r0, __int_as_float(e0.y));
        fma8(acc, r1, __int_as_float(e1.y));
        fma8(acc, r2, __int_as_float(e2.y));
        fma8(acc, r3, __int_as_float(e3.y));
    }
    for (; e < end; e++) {
        int2 ev = __ldg(&g_edge[e]);
        fma8(acc, t16[(size_t)ev.x * 8 + f8], __int_as_float(ev.y));
    }

    // bias + relu -> SMEM h row
    #pragma unroll
    for (int j = 0; j < 8; j++) {
        float v = fmaxf(acc[j] + __ldg(&b2[8 * f8 + j]), 0.f);
        hs[ln * 65 + 8 * f8 + j] = v;
    }
    __syncthreads();

    // FC: this thread computes out[node][c0..c0+7], c0 = 8*f8
    const int c0 = 8 * f8;
    unsigned long long o[4] = {0ull, 0ull, 0ull, 0ull};
    #pragma unroll 4
    for (int f = 0; f < 64; f++) {
        unsigned long long xp = pack2(hs[ln * 65 + f]);
        const float* wrow = &fcWs[f * 64 + c0];
        #pragma unroll
        for (int p = 0; p < 4; p++)
            fma2(o[p], xp, *(const unsigned long long*)(wrow + 2 * p));
    }
    float* orow = out + (size_t)node * 64 + c0;
    #pragma unroll
    for (int p = 0; p < 4; p++) {
        float2 v = unpack2(o[p]);
        float2 bb = *(const float2*)&fcb[c0 + 2 * p];
        ((float2*)orow)[p] = make_float2(v.x + bb.x, v.y + bb.y);
    }
}

// ---------------------------------------------------------------------------
// Launch: CSR build (default stream) overlapped with GEMM1 (side stream)
// ---------------------------------------------------------------------------
extern "C" void kernel_launch(void* const* d_in, const int* in_sizes, int n_in,
                              void* d_out, int out_size) {
    const float* x   = (const float*)d_in[0];
    const void*  ei  = d_in[1];                  // int32 or int64 (detected inline)
    const float* W1  = (const float*)d_in[2];
    const float* b1  = (const float*)d_in[3];
    const float* W2  = (const float*)d_in[4];
    const float* b2  = (const float*)d_in[5];
    const float* fcW = (const float*)d_in[6];
    const float* fcb = (const float*)d_in[7];
    float*       out = (float*)d_out;

    uint4 *t_ptr = nullptr, *h_ptr = nullptr;
    cudaGetSymbolAddress((void**)&t_ptr, g_t16);
    cudaGetSymbolAddress((void**)&h_ptr, g_h16);

    constexpr int SM_G1 = (DIN * DHID + 64 * DIN) * 4;    // 96 KB
    constexpr int SM_G2 = (DHID * DOUT + 64 * DHID) * 4;  // 64 KB

    static cudaStream_t s2 = nullptr;
    static cudaEvent_t  evFork = nullptr, evJoin = nullptr;
    if (!s2) {
        cudaFuncSetAttribute(gemm_kernel<DIN, DHID, false>,
                             cudaFuncAttributeMaxDynamicSharedMemorySize, SM_G1);
        cudaFuncSetAttribute(gemm_kernel<DHID, DOUT, true>,
                             cudaFuncAttributeMaxDynamicSharedMemorySize, SM_G2);
        cudaStreamCreateWithFlags(&s2, cudaStreamNonBlocking);
        cudaEventCreateWithFlags(&evFork, cudaEventDisableTiming);
        cudaEventCreateWithFlags(&evJoin, cudaEventDisableTiming);
    }

    const int TB = 256;
    const int gN    = (NN + TB - 1) / TB;
    const int gE2   = (NE / 2 + TB - 1) / TB;
    const int gGemm = (NN + 63) / 64;

    // --- Fork: GEMM1 on side stream (depends only on x, W1) ---
    cudaEventRecord(evFork, 0);
    cudaStreamWaitEvent(s2, evFork, 0);
    gemm_kernel<DIN, DHID, false><<<gGemm, TB, SM_G1, s2>>>(x, W1, t_ptr, NN);
    cudaEventRecord(evJoin, s2);

    // --- CSR build + normalization on default stream (parallel with GEMM1) ---
    deg_count_kernel<<<gE2, TB>>>(ei);
    alloc_kernel<<<gN, TB>>>();
    fill_kernel<<<gE2, TB>>>(ei);

    // --- Join: gather1 needs both CSR and t ---
    cudaStreamWaitEvent(0, evJoin, 0);
    gather_kernel<DHID, 8><<<(NN + 7) / 8, 128>>>(t_ptr, b1, h_ptr);

    // --- Layer 2 transform (fp16 in, fp16 out) ---
    gemm_kernel<DHID, DOUT, true><<<gGemm, TB, SM_G2>>>(h_ptr, W2, t_ptr, NN);

    // --- Fused gather2 + final FC ---
    gather_fc_kernel<<<NN / 16, 128>>>(t_ptr, b2, fcW, fcb, out);
}

// round 10
// speedup vs baseline: 1.3031x; 1.3031x over previous
#include <cuda_runtime.h>
#include <cuda_fp16.h>

// Problem constants (fixed by the reference)
#define NN   50000
#define NE   800000
#define DIN  128
#define DHID 128
#define DOUT 64

// ---------------------------------------------------------------------------
// Static device scratch (no allocation allowed)
// ---------------------------------------------------------------------------
__device__ int    g_total;                    // running CSR offset (reset in count)
__device__ int    g_deg[NN];                  // zero at start of every replay (self-clean)
__device__ int    g_degs[NN];                 // saved degree for gather
__device__ int    g_cur[NN];
__device__ int    g_rowbeg[NN];               // CSR range start (unordered alloc)
__device__ int    g_csrc[NE];                 // CSR: src per incoming edge
__device__ float  g_dinv[NN];                 // rsqrt(1 + in_degree)
__device__ uint4  g_t16[NN * DHID / 8];       // transform buffer (8 x fp16 per uint4)
__device__ uint4  g_h16[NN * DHID / 8];       // aggregation buffer (8 x fp16 per uint4)

// ---------------------------------------------------------------------------
// f32x2 packed FMA helpers (Blackwell FFMA2 — only reachable via PTX)
// ---------------------------------------------------------------------------
__device__ __forceinline__ unsigned long long pack2(float x) {
    unsigned long long r;
    asm("mov.b64 %0, {%1, %2};" : "=l"(r) : "f"(x), "f"(x));
    return r;
}
__device__ __forceinline__ void fma2(unsigned long long& d,
                                     unsigned long long a, unsigned long long b) {
    asm("fma.rn.f32x2 %0, %1, %2, %0;" : "+l"(d) : "l"(a), "l"(b));
}
__device__ __forceinline__ float2 unpack2(unsigned long long v) {
    float2 f;
    asm("mov.b64 {%0, %1}, %2;" : "=f"(f.x), "=f"(f.y) : "l"(v));
    return f;
}

// ---------------------------------------------------------------------------
// Inline edge-index dtype detection: 4 entries read as int64. True int64
// indices are all in [0, NN); int32 data reinterpreted as int64 only passes
// if every odd word is zero (p ~ (2e-5)^4 ~ 1.6e-19). Broadcast loads, cheap.
// ---------------------------------------------------------------------------
__device__ __forceinline__ bool detect64(const void* __restrict__ ei) {
    const long long* p = (const long long*)ei;
    #pragma unroll
    for (int k = 0; k < 4; k++) {
        long long v = __ldg(&p[k]);
        if (v < 0 || v >= NN) return false;
    }
    return true;
}

// ---------------------------------------------------------------------------
// CSR construction (3 kernels: count -> alloc -> fill)
// ---------------------------------------------------------------------------
// 2 edges per thread; one thread resets g_total for this replay
__global__ void deg_count_kernel(const void* __restrict__ ei) {
    int e2 = blockIdx.x * blockDim.x + threadIdx.x;   // over NE/2
    if (blockIdx.x == 0 && threadIdx.x == 0) g_total = 0;
    if (e2 >= NE / 2) return;
    int d0, d1;
    if (detect64(ei)) {
        longlong2 d = ((const longlong2*)ei)[NE / 2 + e2];
        d0 = (int)d.x; d1 = (int)d.y;
    } else {
        int2 d = ((const int2*)ei)[NE / 2 + e2];
        d0 = d.x; d1 = d.y;
    }
    atomicAdd(&g_deg[d0], 1);
    atomicAdd(&g_deg[d1], 1);
}

// Unordered CSR range allocation; self-cleans g_deg for the next replay.
__global__ void alloc_kernel() {
    int i = blockIdx.x * blockDim.x + threadIdx.x;
    if (i < NN) {
        int d = g_deg[i];
        g_deg[i]    = 0;                      // invariant: zero at next replay start
        g_degs[i]   = d;
        g_rowbeg[i] = atomicAdd(&g_total, d);
        g_dinv[i]   = rsqrtf(1.0f + (float)d);
        g_cur[i]    = 0;
    }
}

// 2 edges per thread; writes src only (4B scattered) — norm computed in gather
__global__ void fill_kernel(const void* __restrict__ ei) {
    int e2 = blockIdx.x * blockDim.x + threadIdx.x;   // over NE/2
    if (e2 >= NE / 2) return;
    int s0, s1, d0, d1;
    if (detect64(ei)) {
        longlong2 s = ((const longlong2*)ei)[e2];
        longlong2 d = ((const longlong2*)ei)[NE / 2 + e2];
        s0 = (int)s.x; s1 = (int)s.y; d0 = (int)d.x; d1 = (int)d.y;
    } else {
        int2 s = ((const int2*)ei)[e2];
        int2 d = ((const int2*)ei)[NE / 2 + e2];
        s0 = s.x; s1 = s.y; d0 = d.x; d1 = d.y;
    }
    int p0 = g_rowbeg[d0] + atomicAdd(&g_cur[d0], 1);
    int p1 = g_rowbeg[d1] + atomicAdd(&g_cur[d1], 1);
    g_csrc[p0] = s0;
    g_csrc[p1] = s1;
}

// ---------------------------------------------------------------------------
// GEMM: Y[M, DO] = X[M, K] @ W[K, DO]  (+ bias if BIAS)
// 64 rows/block, 256 threads, W + X tile in SMEM, FFMA2 accumulation.
// HALF_IN: X is fp16; HALF_OUT: Y stored as half2, else float2.
// ---------------------------------------------------------------------------
template <int K, int DO, bool HALF_IN, bool BIAS, bool HALF_OUT>
__global__ void gemm_kernel(const void* __restrict__ X,
                            const float* __restrict__ W,
                            const float* __restrict__ bias,
                            void* __restrict__ Y, int M) {
    extern __shared__ float sm[];
    float* Ws = sm;            // K * DO
    float* Xs = sm + K * DO;   // 64 * K

    const int tid = threadIdx.x;
    const int bm  = blockIdx.x * 64;

    #pragma unroll 4
    for (int i = tid; i < K * DO / 4; i += 256)
        ((float4*)Ws)[i] = ((const float4*)W)[i];

    #pragma unroll 4
    for (int i = tid; i < 64 * K / 4; i += 256) {
        int row  = i / (K / 4);
        int col4 = i % (K / 4);
        float4 v = make_float4(0.f, 0.f, 0.f, 0.f);
        if (bm + row < M) {
            if (HALF_IN) {
                uint2 rv = *(const uint2*)((const __half*)X + (size_t)(bm + row) * K + col4 * 4);
                float2 a = __half22float2(*(__half2*)&rv.x);
                float2 b = __half22float2(*(__half2*)&rv.y);
                v = make_float4(a.x, a.y, b.x, b.y);
            } else {
                v = ((const float4*)((const float*)X + (size_t)(bm + row) * K))[col4];
            }
        }
        ((float4*)Xs)[i] = v;
    }
    __syncthreads();

    const int tx = tid & 31;
    const int ty = tid >> 5;           // 0..7
    constexpr int CP2 = DO / 64;       // column pairs per thread

    unsigned long long acc[8][CP2];
    #pragma unroll
    for (int r = 0; r < 8; r++)
        #pragma unroll
        for (int c = 0; c < CP2; c++) acc[r][c] = 0ull;

    for (int k = 0; k < K; k += 4) {
        float4 xv[8];
        #pragma unroll
        for (int r = 0; r < 8; r++)
            xv[r] = *(const float4*)&Xs[(ty * 8 + r) * K + k];

        #pragma unroll
        for (int kk = 0; kk < 4; kk++) {
            unsigned long long wv[CP2];
            #pragma unroll
            for (int c = 0; c < CP2; c++)
                wv[c] = *(const unsigned long long*)&Ws[(k + kk) * DO + 2 * tx + 64 * c];
            #pragma unroll
            for (int r = 0; r < 8; r++) {
                float xs = (kk == 0) ? xv[r].x : (kk == 1) ? xv[r].y
                         : (kk == 2) ? xv[r].z : xv[r].w;
                unsigned long long xp = pack2(xs);
                #pragma unroll
                for (int c = 0; c < CP2; c++)
                    fma2(acc[r][c], xp, wv[c]);
            }
        }
    }

    #pragma unroll
    for (int r = 0; r < 8; r++) {
        int row = bm + ty * 8 + r;
        if (row < M) {
            #pragma unroll
            for (int c = 0; c < CP2; c++) {
                float2 v = unpack2(acc[r][c]);
                if (BIAS) {
                    float2 bv = *(const float2*)&bias[2 * tx + 64 * c];
                    v.x += bv.x; v.y += bv.y;
                }
                size_t off = (size_t)row * DO + 2 * tx + 64 * c;
                if (HALF_OUT)
                    *(__half2*)((__half*)Y + off) = __floats2half2_rn(v.x, v.y);
                else
                    *(float2*)((float*)Y + off) = v;
            }
        }
    }
}

// ---------------------------------------------------------------------------
// fp16 row fragment FMA: 8 features per thread
// ---------------------------------------------------------------------------
__device__ __forceinline__ void fma8(float* acc, uint4 raw, float n) {
    float2 p0 = __half22float2(*(__half2*)&raw.x);
    float2 p1 = __half22float2(*(__half2*)&raw.y);
    float2 p2 = __half22float2(*(__half2*)&raw.z);
    float2 p3 = __half22float2(*(__half2*)&raw.w);
    acc[0] = fmaf(p0.x, n, acc[0]); acc[1] = fmaf(p0.y, n, acc[1]);
    acc[2] = fmaf(p1.x, n, acc[2]); acc[3] = fmaf(p1.y, n, acc[3]);
    acc[4] = fmaf(p2.x, n, acc[4]); acc[5] = fmaf(p2.y, n, acc[5]);
    acc[6] = fmaf(p3.x, n, acc[6]); acc[7] = fmaf(p3.y, n, acc[7]);
}

// ---------------------------------------------------------------------------
// Gather aggregation (fused self-loop + bias + ReLU), fp16 in / fp16 out:
//   h[i,f] = relu( t[i,f]*dinv[i]^2 + sum_{s in in(i)} t[s,f]*dinv[s]*dinv[i] + b[f] )
// Each thread owns 8 features (one uint4); D/8 threads per node.
// ---------------------------------------------------------------------------
template <int D, int NPB>   // NPB * (D/8) == 128
__global__ void gather_kernel(const uint4* __restrict__ t16,
                              const float* __restrict__ bias,
                              uint4* __restrict__ h16) {
    constexpr int D8 = D / 8;
    const int ln   = threadIdx.x / D8;
    const int f8   = threadIdx.x % D8;
    const int node = blockIdx.x * NPB + ln;
    if (node >= NN) return;

    const float di  = g_dinv[node];
    const int   beg = g_rowbeg[node];
    const int   end = beg + g_degs[node];

    float acc[8] = {0, 0, 0, 0, 0, 0, 0, 0};
    fma8(acc, t16[(size_t)node * D8 + f8], di * di);   // self loop

    int e = beg;
    for (; e + 4 <= end; e += 4) {
        int s0 = __ldg(&g_csrc[e]);
        int s1 = __ldg(&g_csrc[e + 1]);
        int s2 = __ldg(&g_csrc[e + 2]);
        int s3 = __ldg(&g_csrc[e + 3]);
        uint4 r0 = t16[(size_t)s0 * D8 + f8];
        uint4 r1 = t16[(size_t)s1 * D8 + f8];
        uint4 r2 = t16[(size_t)s2 * D8 + f8];
        uint4 r3 = t16[(size_t)s3 * D8 + f8];
        float n0 = __ldg(&g_dinv[s0]) * di;
        float n1 = __ldg(&g_dinv[s1]) * di;
        float n2 = __ldg(&g_dinv[s2]) * di;
        float n3 = __ldg(&g_dinv[s3]) * di;
        fma8(acc, r0, n0);
        fma8(acc, r1, n1);
        fma8(acc, r2, n2);
        fma8(acc, r3, n3);
    }
    for (; e < end; e++) {
        int s = __ldg(&g_csrc[e]);
        fma8(acc, t16[(size_t)s * D8 + f8], __ldg(&g_dinv[s]) * di);
    }

    float4 b0 = *(const float4*)&bias[8 * f8];
    float4 b1 = *(const float4*)&bias[8 * f8 + 4];
    uint4 o;
    *(__half2*)&o.x = __floats2half2_rn(fmaxf(acc[0] + b0.x, 0.f), fmaxf(acc[1] + b0.y, 0.f));
    *(__half2*)&o.y = __floats2half2_rn(fmaxf(acc[2] + b0.z, 0.f), fmaxf(acc[3] + b0.w, 0.f));
    *(__half2*)&o.z = __floats2half2_rn(fmaxf(acc[4] + b1.x, 0.f), fmaxf(acc[5] + b1.y, 0.f));
    *(__half2*)&o.w = __floats2half2_rn(fmaxf(acc[6] + b1.z, 0.f), fmaxf(acc[7] + b1.w, 0.f));
    h16[(size_t)node * D8 + f8] = o;
}

// ---------------------------------------------------------------------------
// Launch: CSR build (default stream) overlapped with GEMM1 (side stream)
// ---------------------------------------------------------------------------
extern "C" void kernel_launch(void* const* d_in, const int* in_sizes, int n_in,
                              void* d_out, int out_size) {
    const float* x   = (const float*)d_in[0];
    const void*  ei  = d_in[1];                  // int32 or int64 (detected inline)
    const float* W1  = (const float*)d_in[2];
    const float* b1  = (const float*)d_in[3];
    const float* W2  = (const float*)d_in[4];
    const float* b2  = (const float*)d_in[5];
    const float* fcW = (const float*)d_in[6];
    const float* fcb = (const float*)d_in[7];
    float*       out = (float*)d_out;

    uint4 *t_ptr = nullptr, *h_ptr = nullptr;
    cudaGetSymbolAddress((void**)&t_ptr, g_t16);
    cudaGetSymbolAddress((void**)&h_ptr, g_h16);

    constexpr int SM_G1 = (DIN * DHID + 64 * DIN) * 4;    // 96 KB
    constexpr int SM_G2 = (DHID * DOUT + 64 * DHID) * 4;  // 64 KB
    constexpr int SM_G3 = (DOUT * DOUT + 64 * DOUT) * 4;  // 32 KB

    static cudaStream_t s2 = nullptr;
    static cudaEvent_t  evFork = nullptr, evJoin = nullptr;
    if (!s2) {
        cudaFuncSetAttribute(gemm_kernel<DIN, DHID, false, false, true>,
                             cudaFuncAttributeMaxDynamicSharedMemorySize, SM_G1);
        cudaFuncSetAttribute(gemm_kernel<DHID, DOUT, true, false, true>,
                             cudaFuncAttributeMaxDynamicSharedMemorySize, SM_G2);
        cudaFuncSetAttribute(gemm_kernel<DOUT, DOUT, true, true, false>,
                             cudaFuncAttributeMaxDynamicSharedMemorySize, SM_G3);
        cudaStreamCreateWithFlags(&s2, cudaStreamNonBlocking);
        cudaEventCreateWithFlags(&evFork, cudaEventDisableTiming);
        cudaEventCreateWithFlags(&evJoin, cudaEventDisableTiming);
    }

    const int TB = 256;
    const int gN    = (NN + TB - 1) / TB;
    const int gE2   = (NE / 2 + TB - 1) / TB;
    const int gGemm = (NN + 63) / 64;

    // --- Fork: GEMM1 on side stream (depends only on x, W1) ---
    cudaEventRecord(evFork, 0);
    cudaStreamWaitEvent(s2, evFork, 0);
    gemm_kernel<DIN, DHID, false, false, true><<<gGemm, TB, SM_G1, s2>>>(x, W1, nullptr, t_ptr, NN);
    cudaEventRecord(evJoin, s2);

    // --- CSR build + normalization on default stream (parallel with GEMM1) ---
    deg_count_kernel<<<gE2, TB>>>(ei);
    alloc_kernel<<<gN, TB>>>();
    fill_kernel<<<gE2, TB>>>(ei);

    // --- Join: gather1 needs both CSR and t ---
    cudaStreamWaitEvent(0, evJoin, 0);
    gather_kernel<DHID, 8><<<(NN + 7) / 8, 128>>>(t_ptr, b1, h_ptr);

    // --- Layer 2 transform (fp16 in, fp16 out) ---
    gemm_kernel<DHID, DOUT, true, false, true><<<gGemm, TB, SM_G2>>>(h_ptr, W2, nullptr, t_ptr, NN);
    gather_kernel<DOUT, 16><<<(NN + 15) / 16, 128>>>(t_ptr, b2, h_ptr);

    // --- Final FC (fp16 in, fp32 out + bias) ---
    gemm_kernel<DOUT, DOUT, true, true, false><<<gGemm, TB, SM_G3>>>(h_ptr, fcW, fcb, out, NN);
}